// round 1
// baseline (speedup 1.0000x reference)
#include <cuda_runtime.h>
#include <math.h>

// ---------------------------------------------------------------------------
// HyperGraphEncoder baseline (fp32 end-to-end)
// B=256 graphs, H=256, 4 heads x 64; padded lens: atom 127, pharm 23, hyper 11
// ---------------------------------------------------------------------------

namespace {
constexpr int NB   = 256;   // batch (graphs)
constexpr int HD   = 256;   // hidden size H
constexpr int NHEAD = 4;
constexpr int DKH  = 64;    // per-head dim
constexpr int TNA  = 127;   // max atoms
constexpr int TNP  = 23;    // max pharm
constexpr int TNH  = 11;    // max hyper
constexpr int G3   = 768;   // 3*H
}

// -------------------------- device scratch ---------------------------------
__device__ float g_atom_f [NB*TNA*HD];
__device__ float g_pharm_f[NB*TNP*HD];
__device__ float g_hyper_f[NB*TNH*HD];
__device__ float g_q1 [NB*TNP*HD];
__device__ float g_k1 [NB*TNH*HD];
__device__ float g_v1 [NB*TNH*HD];
__device__ float g_o1 [NB*TNP*HD];
__device__ float g_pharm2[NB*TNP*HD];
__device__ float g_q2 [NB*TNA*HD];
__device__ float g_k2 [NB*TNP*HD];
__device__ float g_v2 [NB*TNP*HD];
__device__ float g_o2 [NB*TNA*HD];
__device__ float g_h  [NB*TNA*HD];
__device__ float g_gi_f[(size_t)NB*TNA*G3];
__device__ float g_gi_b[(size_t)NB*TNA*G3];
__device__ float g_hcur[2*NB*HD];     // [dir][b][j]
__device__ float g_gh  [2*NB*G3];     // [dir][b][n]
__device__ float g_outsum[2*NB*HD];
__device__ int   g_starts[3*(NB+1)];

// -------------------------- prefix sums ------------------------------------
__global__ void prefix_kernel(const int* __restrict__ ac,
                              const int* __restrict__ pc,
                              const int* __restrict__ hc) {
    int w = threadIdx.x;
    if (w < 3) {
        const int* c = (w == 0) ? ac : (w == 1) ? pc : hc;
        int* s = g_starts + w * (NB + 1);
        int acc = 0;
        for (int i = 0; i < NB; i++) { s[i] = acc; acc += c[i]; }
        s[NB] = acc;
    }
}

// -------------------------- gather / zero-pad -------------------------------
// grid: (maxN, B), 64 threads; each thread copies one float4 of the 256-float row
__global__ void gather_kernel(const float* __restrict__ msg,
                              const int* __restrict__ counts,
                              int which, float* __restrict__ out, int maxN) {
    int j = blockIdx.x, b = blockIdx.y;
    int cnt = counts[b];
    float4* dst = (float4*)(out + ((size_t)b * maxN + j) * HD);
    if (j < cnt) {
        int src_row = g_starts[which * (NB + 1) + b] + j;
        const float4* src = (const float4*)(msg + (size_t)src_row * HD);
        dst[threadIdx.x] = src[threadIdx.x];
    } else {
        dst[threadIdx.x] = make_float4(0.f, 0.f, 0.f, 0.f);
    }
}

// -------------------------- tiled SGEMM body --------------------------------
// C[M,N] = A[M,K] @ B(+bias)(+resid).  TRANSB: Bm is [N,K] row-major (use Bm^T).
// BM=BN=64, BK=16, 256 threads, 4x4 micro-tile. M,N,K multiples of 64/64/16.
template <bool TRANSB>
__device__ __forceinline__ void sgemm_body(const float* __restrict__ A,
                                           const float* __restrict__ Bm,
                                           const float* __restrict__ bias,
                                           const float* __restrict__ resid,
                                           float* __restrict__ C,
                                           int M, int N, int K, int m0, int n0) {
    constexpr int BK = 16;
    __shared__ float As[BK][64];
    __shared__ float Bs[BK][64];
    int tid = threadIdx.x;
    int tx = tid & 15, ty = tid >> 4;
    float acc[4][4] = {};
    for (int k0 = 0; k0 < K; k0 += BK) {
        {   // load A tile: thread -> (row, 4-float segment)
            int row = tid >> 2, seg = tid & 3;
            float4 a = *(const float4*)&A[(size_t)(m0 + row) * K + k0 + seg * 4];
            As[seg*4+0][row] = a.x; As[seg*4+1][row] = a.y;
            As[seg*4+2][row] = a.z; As[seg*4+3][row] = a.w;
        }
        if (!TRANSB) {
            int row = tid >> 4, seg = tid & 15;
            float4 bv = *(const float4*)&Bm[(size_t)(k0 + row) * N + n0 + seg * 4];
            *(float4*)&Bs[row][seg * 4] = bv;
        } else {
            int n = tid >> 2, seg = tid & 3;
            float4 bv = *(const float4*)&Bm[(size_t)(n0 + n) * K + k0 + seg * 4];
            Bs[seg*4+0][n] = bv.x; Bs[seg*4+1][n] = bv.y;
            Bs[seg*4+2][n] = bv.z; Bs[seg*4+3][n] = bv.w;
        }
        __syncthreads();
#pragma unroll
        for (int k = 0; k < BK; k++) {
            float4 av = *(const float4*)&As[k][ty * 4];
            float4 bv = *(const float4*)&Bs[k][tx * 4];
            float a[4] = {av.x, av.y, av.z, av.w};
            float bb[4] = {bv.x, bv.y, bv.z, bv.w};
#pragma unroll
            for (int i = 0; i < 4; i++)
#pragma unroll
                for (int j = 0; j < 4; j++)
                    acc[i][j] = fmaf(a[i], bb[j], acc[i][j]);
        }
        __syncthreads();
    }
#pragma unroll
    for (int i = 0; i < 4; i++) {
        int m = m0 + ty * 4 + i;
#pragma unroll
        for (int j = 0; j < 4; j++) {
            int n = n0 + tx * 4 + j;
            float v = acc[i][j];
            if (bias)  v += bias[n];
            if (resid) v += resid[(size_t)m * N + n];
            C[(size_t)m * N + n] = v;
        }
    }
}

template <bool TRANSB>
__global__ void __launch_bounds__(256)
sgemm_kernel(const float* __restrict__ A, const float* __restrict__ Bm,
             const float* __restrict__ bias, const float* __restrict__ resid,
             float* __restrict__ C, int M, int N, int K) {
    sgemm_body<TRANSB>(A, Bm, bias, resid, C, M, N, K,
                       blockIdx.y * 64, blockIdx.x * 64);
}

// GRU recurrent GEMM: gh[d] = hcur[d] @ Whh_d^T   (M=256, N=768, K=256)
// grid: (12, 4, 2)
__global__ void __launch_bounds__(256)
gru_gh_kernel(const float* __restrict__ Whh_f, const float* __restrict__ Whh_b) {
    int d = blockIdx.z;
    sgemm_body<true>(g_hcur + (size_t)d * NB * HD,
                     d ? Whh_b : Whh_f,
                     nullptr, nullptr,
                     g_gh + (size_t)d * NB * G3,
                     NB, G3, HD, blockIdx.y * 64, blockIdx.x * 64);
}

// -------------------------- attention ---------------------------------------
// grid: B*NHEAD blocks. One thread per query row. K/V head-slices in smem.
template <int LQ, int LK>
__global__ void attn_kernel(const float* __restrict__ qh,
                            const float* __restrict__ kh,
                            const float* __restrict__ vh,
                            const int* __restrict__ qc,
                            const int* __restrict__ kc,
                            float* __restrict__ o) {
    __shared__ float ks[LK * DKH];
    __shared__ float vs[LK * DKH];
    int bh = blockIdx.x;
    int b = bh / NHEAD, hd = bh % NHEAD;
    for (int idx = threadIdx.x; idx < LK * DKH; idx += blockDim.x) {
        int k = idx / DKH, i = idx % DKH;
        size_t base = ((size_t)(b * LK) + k) * HD + hd * DKH + i;
        ks[idx] = kh[base];
        vs[idx] = vh[base];
    }
    __syncthreads();
    int q = threadIdx.x;
    if (q >= LQ) return;

    float qreg[DKH];
    const float* qp = &qh[((size_t)(b * LQ) + q) * HD + hd * DKH];
#pragma unroll
    for (int i = 0; i < DKH; i++) qreg[i] = qp[i];

    bool vq = q < qc[b];
    int kcnt = kc[b];
    float s[LK];
    float mx = -3.402823e38f;
#pragma unroll
    for (int k = 0; k < LK; k++) {
        float d = 0.f;
#pragma unroll
        for (int i = 0; i < DKH; i++) d = fmaf(qreg[i], ks[k * DKH + i], d);
        float val = (vq && k < kcnt) ? d * 0.125f : -1e9f;
        s[k] = val;
        mx = fmaxf(mx, val);
    }
    float sum = 0.f;
#pragma unroll
    for (int k = 0; k < LK; k++) { s[k] = expf(s[k] - mx); sum += s[k]; }
    float inv = 1.f / sum;
    float* op = &o[((size_t)(b * LQ) + q) * HD + hd * DKH];
#pragma unroll
    for (int i = 0; i < DKH; i++) {
        float a = 0.f;
#pragma unroll
        for (int k = 0; k < LK; k++) a = fmaf(s[k], vs[k * DKH + i], a);
        op[i] = a * inv;
    }
}

// -------------------------- h0 = max over t ---------------------------------
__global__ void hmax_kernel() {
    int b = blockIdx.x, j = threadIdx.x;
    float m = -3.402823e38f;
    for (int t = 0; t < TNA; t++)
        m = fmaxf(m, g_h[((size_t)(b * TNA) + t) * HD + j]);
    g_hcur[(size_t)b * HD + j] = m;
    g_hcur[(size_t)NB * HD + (size_t)b * HD + j] = m;
}

// -------------------------- GRU gate update ---------------------------------
__global__ void __launch_bounds__(256)
gru_gate_kernel(const float* __restrict__ bhh_f, const float* __restrict__ bhh_b,
                const int* __restrict__ counts, int t) {
    int idx = blockIdx.x * blockDim.x + threadIdx.x;   // 0 .. 2*256*256-1
    int d = idx >> 16;
    int b = (idx >> 8) & 255;
    int j = idx & 255;
    int teff = d ? (TNA - 1 - t) : t;
    const float* gi = (d ? g_gi_b : g_gi_f) + ((size_t)(b * TNA) + teff) * G3;
    const float* bhh = d ? bhh_b : bhh_f;
    const float* gh = g_gh + (size_t)d * NB * G3 + (size_t)b * G3;
    float ir = gi[j], iz = gi[j + 256], in = gi[j + 512];
    float hr = gh[j] + bhh[j];
    float hz = gh[j + 256] + bhh[j + 256];
    float hn = gh[j + 512] + bhh[j + 512];
    float r = 1.f / (1.f + expf(-(ir + hr)));
    float z = 1.f / (1.f + expf(-(iz + hz)));
    float n = tanhf(in + r * hn);
    size_t hidx = (size_t)d * NB * HD + (size_t)b * HD + j;
    float hp = g_hcur[hidx];
    float h = (1.f - z) * n + z * hp;
    g_hcur[hidx] = h;
    if (teff < counts[b]) g_outsum[hidx] += h;
}

__global__ void zero_outsum_kernel() {
    int idx = blockIdx.x * blockDim.x + threadIdx.x;
    g_outsum[idx] = 0.f;
}

__global__ void final_kernel(const int* __restrict__ counts, float* __restrict__ out) {
    int idx = blockIdx.x * blockDim.x + threadIdx.x;   // 0 .. 2*256*256-1
    int d = idx >> 16;
    int b = (idx >> 8) & 255;
    int j = idx & 255;
    float c = (float)counts[b];
    out[(size_t)b * 512 + d * 256 + j] =
        g_outsum[(size_t)d * NB * HD + (size_t)b * HD + j] / c;
}

// -------------------------- host launch -------------------------------------
static float* symaddr(const void* sym) {
    void* p = nullptr;
    cudaGetSymbolAddress(&p, sym);
    return (float*)p;
}

extern "C" void kernel_launch(void* const* d_in, const int* in_sizes, int n_in,
                              void* d_out, int out_size) {
    // Input layout detection: dict order (counts at 3..5) vs signature order
    // (counts at end).
    int wbase, ci0, ci1, ci2;
    if (in_sizes[3] == NB) { ci0 = 3; ci1 = 4; ci2 = 5; wbase = 6; }
    else { wbase = 3; ci0 = n_in - 3; ci1 = n_in - 2; ci2 = n_in - 1; }

    const float* atom_msg  = (const float*)d_in[0];
    const float* pharm_msg = (const float*)d_in[1];
    const float* hyper_msg = (const float*)d_in[2];
    const int* ac = (const int*)d_in[ci0];
    const int* pc = (const int*)d_in[ci1];
    const int* hc = (const int*)d_in[ci2];

    const float* p2h[8];
    const float* a2p[8];
    for (int i = 0; i < 8; i++) p2h[i] = (const float*)d_in[wbase + i];
    for (int i = 0; i < 8; i++) a2p[i] = (const float*)d_in[wbase + 8 + i];
    const float* Wih_f = (const float*)d_in[wbase + 16];
    const float* Whh_f = (const float*)d_in[wbase + 17];
    const float* bih_f = (const float*)d_in[wbase + 18];
    const float* bhh_f = (const float*)d_in[wbase + 19];
    const float* Wih_b = (const float*)d_in[wbase + 20];
    const float* Whh_b = (const float*)d_in[wbase + 21];
    const float* bih_b = (const float*)d_in[wbase + 22];
    const float* bhh_b = (const float*)d_in[wbase + 23];

    float* atom_f  = symaddr(g_atom_f);
    float* pharm_f = symaddr(g_pharm_f);
    float* hyper_f = symaddr(g_hyper_f);
    float* q1 = symaddr(g_q1);
    float* k1 = symaddr(g_k1);
    float* v1 = symaddr(g_v1);
    float* o1 = symaddr(g_o1);
    float* pharm2 = symaddr(g_pharm2);
    float* q2 = symaddr(g_q2);
    float* k2 = symaddr(g_k2);
    float* v2 = symaddr(g_v2);
    float* o2 = symaddr(g_o2);
    float* hbuf = symaddr(g_h);
    float* gi_f = symaddr(g_gi_f);
    float* gi_b = symaddr(g_gi_b);

    float* out = (float*)d_out;

    const int MA = NB * TNA;   // 32512
    const int MP = NB * TNP;   // 5888
    const int MH = NB * TNH;   // 2816

    // 1. prefix sums
    prefix_kernel<<<1, 32>>>(ac, pc, hc);

    // 2. gather + zero pad
    gather_kernel<<<dim3(TNA, NB), 64>>>(atom_msg,  ac, 0, atom_f,  TNA);
    gather_kernel<<<dim3(TNP, NB), 64>>>(pharm_msg, pc, 1, pharm_f, TNP);
    gather_kernel<<<dim3(TNH, NB), 64>>>(hyper_msg, hc, 2, hyper_f, TNH);

    // 3. MHA1 (pharm queries, hyper kv)
    sgemm_kernel<false><<<dim3(HD/64, MP/64), 256>>>(pharm_f, p2h[0], p2h[1], nullptr, q1, MP, HD, HD);
    sgemm_kernel<false><<<dim3(HD/64, MH/64), 256>>>(hyper_f, p2h[2], p2h[3], nullptr, k1, MH, HD, HD);
    sgemm_kernel<false><<<dim3(HD/64, MH/64), 256>>>(hyper_f, p2h[4], p2h[5], nullptr, v1, MH, HD, HD);
    attn_kernel<TNP, TNH><<<NB * NHEAD, 32>>>(q1, k1, v1, pc, hc, o1);
    sgemm_kernel<false><<<dim3(HD/64, MP/64), 256>>>(o1, p2h[6], p2h[7], pharm_f, pharm2, MP, HD, HD);

    // 4. MHA2 (atom queries, updated-pharm kv)
    sgemm_kernel<false><<<dim3(HD/64, MA/64), 256>>>(atom_f, a2p[0], a2p[1], nullptr, q2, MA, HD, HD);
    sgemm_kernel<false><<<dim3(HD/64, MP/64), 256>>>(pharm2, a2p[2], a2p[3], nullptr, k2, MP, HD, HD);
    sgemm_kernel<false><<<dim3(HD/64, MP/64), 256>>>(pharm2, a2p[4], a2p[5], nullptr, v2, MP, HD, HD);
    attn_kernel<TNA, TNP><<<NB * NHEAD, 128>>>(q2, k2, v2, ac, pc, o2);
    sgemm_kernel<false><<<dim3(HD/64, MA/64), 256>>>(o2, a2p[6], a2p[7], atom_f, hbuf, MA, HD, HD);

    // 5. h0 = max over t (both GRU directions)
    hmax_kernel<<<NB, HD>>>();

    // 6. GRU input precompute gi = h @ Wih^T + bih (per direction)
    sgemm_kernel<true><<<dim3(G3/64, MA/64), 256>>>(hbuf, Wih_f, bih_f, nullptr, gi_f, MA, G3, HD);
    sgemm_kernel<true><<<dim3(G3/64, MA/64), 256>>>(hbuf, Wih_b, bih_b, nullptr, gi_b, MA, G3, HD);

    // 7. GRU recurrence (both directions per step), accumulate valid sums
    zero_outsum_kernel<<<(2 * NB * HD) / 256, 256>>>();
    for (int t = 0; t < TNA; t++) {
        gru_gh_kernel<<<dim3(G3/64, NB/64, 2), 256>>>(Whh_f, Whh_b);
        gru_gate_kernel<<<(2 * NB * HD) / 256, 256>>>(bhh_f, bhh_b, ac, t);
    }

    // 8. masked mean -> output [256, 512]
    final_kernel<<<(2 * NB * HD) / 256, 256>>>(ac, out);
    (void)out_size; (void)n_in;
}